// round 11
// baseline (speedup 1.0000x reference)
#include <cuda_runtime.h>
#include <cuda_fp16.h>
#include <cstdint>

#define N_NODES 100000
#define N_EDGES 3200000
#define D_IN    128
#define D_OUT   64
#define CAP     96      // max in-degree bucket capacity (actual max ~58 for Poisson(32))

// ---------------- scratch (static device globals; no allocation) ----------------
__device__ unsigned g_zh  [(size_t)N_NODES * 32];      // z as half2 (64 cols -> 32 words), 12.8 MB
__device__ float    g_ezs [N_NODES];                   // exp(z . a[:64])
__device__ float    g_ezd [N_NODES];                   // exp(z . a[64:])
__device__ int      g_cnt [N_NODES];                   // bucket fill counts
__device__ int2     g_perm[(size_t)N_NODES * CAP];     // (src, bitcast(w)) buckets, 76.8 MB

// ---------------- K1: z = h @ W (64x64 tile, 4x4 thread tile) ----------------------
__global__ __launch_bounds__(256) void k_gemm(const float* __restrict__ h,
                                              const float* __restrict__ W,
                                              const float* __restrict__ a) {
    __shared__ float sh[64][D_IN];      // 32 KB, node-major (M-frags broadcast)
    __shared__ float sW[D_IN][D_OUT];   // 32 KB, k-major  (N-frags conflict-free)

    int t = threadIdx.x;
    {
        const float4* W4 = (const float4*)W;
        float4* sW4 = (float4*)sW;
        #pragma unroll
        for (int i = 0; i < 8; ++i) sW4[t + i * 256] = W4[t + i * 256];
    }
    {
        const float4* h4 = (const float4*)h;
        float4* sh4 = (float4*)sh;
        int base = blockIdx.x * 2048;
        const int maxi = N_NODES * 32 - 1;   // h = 3.2M float4
        #pragma unroll
        for (int i = 0; i < 8; ++i) {
            int gi = base + t + i * 256;
            sh4[t + i * 256] = h4[gi <= maxi ? gi : maxi];
        }
    }
    __syncthreads();

    int tn = t & 15;          // column group: cols c0..c0+3
    int tm = t >> 4;          // node group:   rows m0..m0+3
    int c0 = tn * 4;
    int m0 = tm * 4;

    float acc[4][4] = {};
    #pragma unroll 4
    for (int k = 0; k < D_IN; k += 4) {
        float4 wn0 = *(const float4*)&sW[k + 0][c0];
        float4 wn1 = *(const float4*)&sW[k + 1][c0];
        float4 wn2 = *(const float4*)&sW[k + 2][c0];
        float4 wn3 = *(const float4*)&sW[k + 3][c0];
        #pragma unroll
        for (int r = 0; r < 4; ++r) {
            float4 hm = *(const float4*)&sh[m0 + r][k];   // broadcast across tn
            acc[r][0] = fmaf(hm.x, wn0.x, fmaf(hm.y, wn1.x, fmaf(hm.z, wn2.x, fmaf(hm.w, wn3.x, acc[r][0]))));
            acc[r][1] = fmaf(hm.x, wn0.y, fmaf(hm.y, wn1.y, fmaf(hm.z, wn2.y, fmaf(hm.w, wn3.y, acc[r][1]))));
            acc[r][2] = fmaf(hm.x, wn0.z, fmaf(hm.y, wn1.z, fmaf(hm.z, wn2.z, fmaf(hm.w, wn3.z, acc[r][2]))));
            acc[r][3] = fmaf(hm.x, wn0.w, fmaf(hm.y, wn1.w, fmaf(hm.z, wn2.w, fmaf(hm.w, wn3.w, acc[r][3]))));
        }
    }

    int n0 = blockIdx.x * 64;
    float4 as = *(const float4*)&a[c0];
    float4 ad = *(const float4*)&a[64 + c0];

    #pragma unroll
    for (int r = 0; r < 4; ++r) {
        int n = n0 + m0 + r;
        bool valid = (n < N_NODES);
        if (valid) {
            __half2 p0 = __floats2half2_rn(acc[r][0], acc[r][1]);
            __half2 p1 = __floats2half2_rn(acc[r][2], acc[r][3]);
            unsigned* dstw = &g_zh[(size_t)n * 32 + (c0 >> 1)];
            dstw[0] = *(unsigned*)&p0;
            dstw[1] = *(unsigned*)&p1;
        }
        float zs = acc[r][0] * as.x + acc[r][1] * as.y + acc[r][2] * as.z + acc[r][3] * as.w;
        float zd = acc[r][0] * ad.x + acc[r][1] * ad.y + acc[r][2] * ad.z + acc[r][3] * ad.w;
        #pragma unroll
        for (int o = 8; o > 0; o >>= 1) {
            zs += __shfl_xor_sync(0xffffffffu, zs, o);
            zd += __shfl_xor_sync(0xffffffffu, zd, o);
        }
        if (tn == 0 && valid) {
            g_ezs[n] = __expf(zs);
            g_ezd[n] = __expf(zd);
            g_cnt[n] = 0;                   // fused zeroing (ordered by kernel boundary)
        }
    }
}

// ---------------- K2: edge pass (8 edges/thread): w = ezs[s]*ezd[d], bucket drop -------
__global__ void k_edge(const int* __restrict__ src, const int* __restrict__ dst) {
    int i = blockIdx.x * blockDim.x + threadIdx.x;   // octet index
    if (i * 8 >= N_EDGES) return;
    int4 sa = ((const int4*)src)[2 * i];
    int4 sb = ((const int4*)src)[2 * i + 1];
    int4 da = ((const int4*)dst)[2 * i];
    int4 db = ((const int4*)dst)[2 * i + 1];
    // 16 gathers in flight
    float a0 = g_ezs[sa.x], b0 = g_ezd[da.x];
    float a1 = g_ezs[sa.y], b1 = g_ezd[da.y];
    float a2 = g_ezs[sa.z], b2 = g_ezd[da.z];
    float a3 = g_ezs[sa.w], b3 = g_ezd[da.w];
    float a4 = g_ezs[sb.x], b4 = g_ezd[db.x];
    float a5 = g_ezs[sb.y], b5 = g_ezd[db.y];
    float a6 = g_ezs[sb.z], b6 = g_ezd[db.z];
    float a7 = g_ezs[sb.w], b7 = g_ezd[db.w];
    int p0 = atomicAdd(&g_cnt[da.x], 1);
    int p1 = atomicAdd(&g_cnt[da.y], 1);
    int p2 = atomicAdd(&g_cnt[da.z], 1);
    int p3 = atomicAdd(&g_cnt[da.w], 1);
    int p4 = atomicAdd(&g_cnt[db.x], 1);
    int p5 = atomicAdd(&g_cnt[db.y], 1);
    int p6 = atomicAdd(&g_cnt[db.z], 1);
    int p7 = atomicAdd(&g_cnt[db.w], 1);
    g_perm[da.x * CAP + p0] = make_int2(sa.x, __float_as_int(a0 * b0));
    g_perm[da.y * CAP + p1] = make_int2(sa.y, __float_as_int(a1 * b1));
    g_perm[da.z * CAP + p2] = make_int2(sa.z, __float_as_int(a2 * b2));
    g_perm[da.w * CAP + p3] = make_int2(sa.w, __float_as_int(a3 * b3));
    g_perm[db.x * CAP + p4] = make_int2(sb.x, __float_as_int(a4 * b4));
    g_perm[db.y * CAP + p5] = make_int2(sb.y, __float_as_int(a5 * b5));
    g_perm[db.z * CAP + p6] = make_int2(sb.z, __float_as_int(a6 * b6));
    g_perm[db.w * CAP + p7] = make_int2(sb.w, __float_as_int(a7 * b7));
}

// ---------------- K3: warp-per-node accumulate, 2-stage software pipeline -----------
// fp16 z row = 128B = 32 lanes x one half2; lane owns 2 output columns.
// Stage layout per iteration q: prefetch bucket[q+2]; issue z loads for quad q+1
// (bucket already resident from 2 iterations ago); consume quad q. No address
// computation ever waits on an in-flight load.
__global__ __launch_bounds__(256) void k_accum(float* __restrict__ out) {
    int gw   = (blockIdx.x * 256 + threadIdx.x) >> 5;
    int lane = threadIdx.x & 31;
    if (gw >= N_NODES) return;
    int cnt  = g_cnt[gw];
    const int2* bucket = g_perm + (size_t)gw * CAP;
    const int4* b4     = (const int4*)bucket;

    float acc0 = 0.0f, acc1 = 0.0f, den = 0.0f;
    int nq = cnt >> 2;
    if (nq > 0) {
        // quad 0: bucket + z loads
        int4 ba = b4[0], bb = b4[1];
        unsigned u0 = g_zh[ba.x * 32 + lane];
        unsigned u1 = g_zh[ba.z * 32 + lane];
        unsigned u2 = g_zh[bb.x * 32 + lane];
        unsigned u3 = g_zh[bb.z * 32 + lane];
        // quad 1 bucket (in flight while quad 0 consumed)
        int4 na, nb;
        {
            int qi = (nq > 1) ? 2 : 0;
            na = b4[qi]; nb = b4[qi + 1];
        }
        #pragma unroll 1
        for (int q = 0; q + 1 < nq; ++q) {
            // stage A: prefetch bucket for quad q+2 (clamped re-read if none)
            int qi = (q + 2 < nq) ? (2 * q + 4) : (2 * q + 2);
            int4 fa = b4[qi], fb = b4[qi + 1];
            // stage B: issue z loads for quad q+1 (na/nb resident)
            unsigned v0 = g_zh[na.x * 32 + lane];
            unsigned v1 = g_zh[na.z * 32 + lane];
            unsigned v2 = g_zh[nb.x * 32 + lane];
            unsigned v3 = g_zh[nb.z * 32 + lane];
            // stage C: consume quad q
            float w0 = __int_as_float(ba.y), w1 = __int_as_float(ba.w);
            float w2 = __int_as_float(bb.y), w3 = __int_as_float(bb.w);
            float2 f0 = __half22float2(*(__half2*)&u0);
            float2 f1 = __half22float2(*(__half2*)&u1);
            float2 f2 = __half22float2(*(__half2*)&u2);
            float2 f3 = __half22float2(*(__half2*)&u3);
            acc0 = fmaf(w0, f0.x, acc0); acc1 = fmaf(w0, f0.y, acc1);
            acc0 = fmaf(w1, f1.x, acc0); acc1 = fmaf(w1, f1.y, acc1);
            acc0 = fmaf(w2, f2.x, acc0); acc1 = fmaf(w2, f2.y, acc1);
            acc0 = fmaf(w3, f3.x, acc0); acc1 = fmaf(w3, f3.y, acc1);
            den += (w0 + w1) + (w2 + w3);
            ba = na; bb = nb; na = fa; nb = fb;
            u0 = v0; u1 = v1; u2 = v2; u3 = v3;
        }
        // consume final quad
        float w0 = __int_as_float(ba.y), w1 = __int_as_float(ba.w);
        float w2 = __int_as_float(bb.y), w3 = __int_as_float(bb.w);
        float2 f0 = __half22float2(*(__half2*)&u0);
        float2 f1 = __half22float2(*(__half2*)&u1);
        float2 f2 = __half22float2(*(__half2*)&u2);
        float2 f3 = __half22float2(*(__half2*)&u3);
        acc0 = fmaf(w0, f0.x, acc0); acc1 = fmaf(w0, f0.y, acc1);
        acc0 = fmaf(w1, f1.x, acc0); acc1 = fmaf(w1, f1.y, acc1);
        acc0 = fmaf(w2, f2.x, acc0); acc1 = fmaf(w2, f2.y, acc1);
        acc0 = fmaf(w3, f3.x, acc0); acc1 = fmaf(w3, f3.y, acc1);
        den += (w0 + w1) + (w2 + w3);
    }
    for (int j = nq << 2; j < cnt; ++j) {          // fp32 tail
        int2 p = bucket[j];
        unsigned u = g_zh[p.x * 32 + lane];
        float w = __int_as_float(p.y);
        float2 f = __half22float2(*(__half2*)&u);
        acc0 = fmaf(w, f.x, acc0); acc1 = fmaf(w, f.y, acc1);
        den += w;
    }
    float inv = (cnt > 0) ? (1.0f / den) : 0.0f;
    float2 res = make_float2(acc0 * inv, acc1 * inv);
    ((float2*)out)[(size_t)gw * 32 + lane] = res;
}

// ---------------- launch ----------------
extern "C" void kernel_launch(void* const* d_in, const int* in_sizes, int n_in,
                              void* d_out, int out_size) {
    const float* h   = (const float*)d_in[0];
    const float* W   = (const float*)d_in[1];
    const float* a   = (const float*)d_in[2];
    const int*   src = (const int*)d_in[3];
    const int*   dst = (const int*)d_in[4];
    float* out = (float*)d_out;
    (void)in_sizes; (void)n_in; (void)out_size;

    k_gemm<<<(N_NODES + 63) / 64, 256>>>(h, W, a);             // also zeroes g_cnt
    k_edge<<<((N_EDGES / 8) + 255) / 256, 256>>>(src, dst);    // 8 edges / thread
    k_accum<<<(N_NODES * 32 + 255) / 256, 256>>>(out);
}

// round 12
// speedup vs baseline: 1.1689x; 1.1689x over previous
#include <cuda_runtime.h>
#include <cuda_fp16.h>
#include <cstdint>

#define N_NODES 100000
#define N_EDGES 3200000
#define D_IN    128
#define D_OUT   64
#define CAP     96      // max in-degree bucket capacity (actual max ~58 for Poisson(32))

// ---------------- scratch (static device globals; no allocation) ----------------
__device__ unsigned g_zh  [(size_t)N_NODES * 32];      // z as half2 (64 cols -> 32 words), 12.8 MB
__device__ float    g_ezs [N_NODES];                   // exp(h . va)
__device__ float    g_ezd [N_NODES];                   // exp(h . vd)
__device__ int      g_cnt [N_NODES];                   // bucket fill counts
__device__ int2     g_perm[(size_t)N_NODES * CAP];     // (src, bitcast(w)) buckets, 76.8 MB
__device__ uint2    g_wf  [8 * 8 * 32];                // W as HMMA B-fragments [kstep][ntile][lane]
__device__ float    g_va  [D_IN];                      // W @ a[:64]
__device__ float    g_vd  [D_IN];                      // W @ a[64:]

// ---------------- K0: prep — W fragments + projected attention vectors ----------------
__global__ void k_prep(const float* __restrict__ W, const float* __restrict__ a) {
    if (blockIdx.x < 8) {
        int t = blockIdx.x * 256 + threadIdx.x;       // 0..2047 = [kstep][ntile][lane]
        int lane = t & 31;
        int gid = lane >> 2, tig = lane & 3;
        int rest = t >> 5;
        int ntile = rest & 7, kstep = rest >> 3;
        int k0 = kstep * 16 + tig * 2;
        int n  = ntile * 8 + gid;
        // B frag (col-major k16n8): b0 = {W[k0][n], W[k0+1][n]}, b1 = {W[k0+8][n], W[k0+9][n]}
        __half2 b0 = __floats2half2_rn(W[k0 * 64 + n],       W[(k0 + 1) * 64 + n]);
        __half2 b1 = __floats2half2_rn(W[(k0 + 8) * 64 + n], W[(k0 + 9) * 64 + n]);
        g_wf[t] = make_uint2(*(unsigned*)&b0, *(unsigned*)&b1);
    } else {
        int k = threadIdx.x;
        if (k < D_IN) {
            float sa = 0.0f, sd = 0.0f;
            #pragma unroll 8
            for (int n = 0; n < 64; ++n) {
                float w = W[k * 64 + n];
                sa = fmaf(w, a[n], sa);
                sd = fmaf(w, a[64 + n], sd);
            }
            g_va[k] = sa;
            g_vd[k] = sd;
        }
    }
}

// ---------------- K1: z = h @ W via HMMA m16n8k16; fused exp(h.va)/exp(h.vd) ----------
// 8 warps/block, warp = 16 nodes x 64 cols. A frags straight from gmem (fp32->f16x2).
__global__ __launch_bounds__(256) void k_gemm(const float* __restrict__ h) {
    int warp = threadIdx.x >> 5, lane = threadIdx.x & 31;
    int gid = lane >> 2, tig = lane & 3;
    int M0 = blockIdx.x * 128 + warp * 16;
    if (M0 >= N_NODES) return;                         // 100000 % 16 == 0: full tiles only
    const float* rowA = h + (size_t)(M0 + gid) * D_IN;
    const float* rowB = h + (size_t)(M0 + 8 + gid) * D_IN;

    float d[8][4] = {};                                // [ntile][c0..c3]
    float zsA = 0.0f, zdA = 0.0f, zsB = 0.0f, zdB = 0.0f;

    #pragma unroll
    for (int ks = 0; ks < 8; ++ks) {
        int kA = ks * 16 + tig * 2;
        float2 fa0 = *(const float2*)&rowA[kA];        // A[gid][kA..+1]
        float2 fa1 = *(const float2*)&rowB[kA];        // A[gid+8][kA..+1]
        float2 fa2 = *(const float2*)&rowA[kA + 8];    // A[gid][kA+8..+9]
        float2 fa3 = *(const float2*)&rowB[kA + 8];    // A[gid+8][kA+8..+9]
        // exact fp32 logit partials: zs = h . va, zd = h . vd
        float2 vaL = *(const float2*)&g_va[kA];
        float2 vaH = *(const float2*)&g_va[kA + 8];
        float2 vdL = *(const float2*)&g_vd[kA];
        float2 vdH = *(const float2*)&g_vd[kA + 8];
        zsA = fmaf(fa0.x, vaL.x, fmaf(fa0.y, vaL.y, fmaf(fa2.x, vaH.x, fmaf(fa2.y, vaH.y, zsA))));
        zdA = fmaf(fa0.x, vdL.x, fmaf(fa0.y, vdL.y, fmaf(fa2.x, vdH.x, fmaf(fa2.y, vdH.y, zdA))));
        zsB = fmaf(fa1.x, vaL.x, fmaf(fa1.y, vaL.y, fmaf(fa3.x, vaH.x, fmaf(fa3.y, vaH.y, zsB))));
        zdB = fmaf(fa1.x, vdL.x, fmaf(fa1.y, vdL.y, fmaf(fa3.x, vdH.x, fmaf(fa3.y, vdH.y, zdB))));
        // pack A frags to f16x2
        __half2 ha0 = __floats2half2_rn(fa0.x, fa0.y);
        __half2 ha1 = __floats2half2_rn(fa1.x, fa1.y);
        __half2 ha2 = __floats2half2_rn(fa2.x, fa2.y);
        __half2 ha3 = __floats2half2_rn(fa3.x, fa3.y);
        unsigned a0 = *(unsigned*)&ha0, a1 = *(unsigned*)&ha1;
        unsigned a2 = *(unsigned*)&ha2, a3 = *(unsigned*)&ha3;
        const uint2* wf = &g_wf[ks * 256 + lane];
        #pragma unroll
        for (int nt = 0; nt < 8; ++nt) {
            uint2 b = wf[nt * 32];
            asm volatile(
                "mma.sync.aligned.m16n8k16.row.col.f32.f16.f16.f32 "
                "{%0,%1,%2,%3}, {%4,%5,%6,%7}, {%8,%9}, {%0,%1,%2,%3};"
                : "+f"(d[nt][0]), "+f"(d[nt][1]), "+f"(d[nt][2]), "+f"(d[nt][3])
                : "r"(a0), "r"(a1), "r"(a2), "r"(a3), "r"(b.x), "r"(b.y));
        }
    }

    // z store: row M0+gid cols nt*8+tig*2(,+1) -> word nt*4+tig; row M0+8+gid from c2,c3
    unsigned* zr0 = &g_zh[(size_t)(M0 + gid) * 32];
    unsigned* zr1 = &g_zh[(size_t)(M0 + 8 + gid) * 32];
    #pragma unroll
    for (int nt = 0; nt < 8; ++nt) {
        __half2 p0 = __floats2half2_rn(d[nt][0], d[nt][1]);
        __half2 p1 = __floats2half2_rn(d[nt][2], d[nt][3]);
        zr0[nt * 4 + tig] = *(unsigned*)&p0;
        zr1[nt * 4 + tig] = *(unsigned*)&p1;
    }
    // reduce logits across the 4-lane tig group
    zsA += __shfl_xor_sync(0xffffffffu, zsA, 1); zsA += __shfl_xor_sync(0xffffffffu, zsA, 2);
    zdA += __shfl_xor_sync(0xffffffffu, zdA, 1); zdA += __shfl_xor_sync(0xffffffffu, zdA, 2);
    zsB += __shfl_xor_sync(0xffffffffu, zsB, 1); zsB += __shfl_xor_sync(0xffffffffu, zsB, 2);
    zdB += __shfl_xor_sync(0xffffffffu, zdB, 1); zdB += __shfl_xor_sync(0xffffffffu, zdB, 2);
    if (tig == 0) {
        int n1 = M0 + gid, n2 = M0 + 8 + gid;
        g_ezs[n1] = __expf(zsA); g_ezd[n1] = __expf(zdA); g_cnt[n1] = 0;
        g_ezs[n2] = __expf(zsB); g_ezd[n2] = __expf(zdB); g_cnt[n2] = 0;
    }
}

// ---------------- K2: edge pass (4 edges/thread): w = ezs[s]*ezd[d], bucket drop -------
__global__ void k_edge(const int* __restrict__ src, const int* __restrict__ dst) {
    int i = blockIdx.x * blockDim.x + threadIdx.x;   // quad index
    if (i * 4 >= N_EDGES) return;
    int4 s4 = ((const int4*)src)[i];
    int4 d4 = ((const int4*)dst)[i];
    float a0 = g_ezs[s4.x], b0 = g_ezd[d4.x];
    float a1 = g_ezs[s4.y], b1 = g_ezd[d4.y];
    float a2 = g_ezs[s4.z], b2 = g_ezd[d4.z];
    float a3 = g_ezs[s4.w], b3 = g_ezd[d4.w];
    float w0 = a0 * b0, w1 = a1 * b1, w2 = a2 * b2, w3 = a3 * b3;
    int p0 = atomicAdd(&g_cnt[d4.x], 1);
    int p1 = atomicAdd(&g_cnt[d4.y], 1);
    int p2 = atomicAdd(&g_cnt[d4.z], 1);
    int p3 = atomicAdd(&g_cnt[d4.w], 1);
    g_perm[d4.x * CAP + p0] = make_int2(s4.x, __float_as_int(w0));
    g_perm[d4.y * CAP + p1] = make_int2(s4.y, __float_as_int(w1));
    g_perm[d4.z * CAP + p2] = make_int2(s4.z, __float_as_int(w2));
    g_perm[d4.w * CAP + p3] = make_int2(s4.w, __float_as_int(w3));
}

// ---------------- K3: warp-per-node accumulate (fp32 quad loop, known-good) ----------
__global__ __launch_bounds__(256) void k_accum(float* __restrict__ out) {
    int gw   = (blockIdx.x * 256 + threadIdx.x) >> 5;
    int lane = threadIdx.x & 31;
    if (gw >= N_NODES) return;
    int cnt  = g_cnt[gw];
    const int2* bucket = g_perm + (size_t)gw * CAP;
    const int4* b4     = (const int4*)bucket;

    float acc0 = 0.0f, acc1 = 0.0f, den = 0.0f;
    int nq = cnt >> 2;
    #pragma unroll 1
    for (int q = 0; q < nq; ++q) {
        int4 ba = b4[2 * q];
        int4 bb = b4[2 * q + 1];
        unsigned u0 = g_zh[ba.x * 32 + lane];
        unsigned u1 = g_zh[ba.z * 32 + lane];
        unsigned u2 = g_zh[bb.x * 32 + lane];
        unsigned u3 = g_zh[bb.z * 32 + lane];
        float w0 = __int_as_float(ba.y), w1 = __int_as_float(ba.w);
        float w2 = __int_as_float(bb.y), w3 = __int_as_float(bb.w);
        float2 f0 = __half22float2(*(__half2*)&u0);
        float2 f1 = __half22float2(*(__half2*)&u1);
        float2 f2 = __half22float2(*(__half2*)&u2);
        float2 f3 = __half22float2(*(__half2*)&u3);
        acc0 = fmaf(w0, f0.x, acc0); acc1 = fmaf(w0, f0.y, acc1);
        acc0 = fmaf(w1, f1.x, acc0); acc1 = fmaf(w1, f1.y, acc1);
        acc0 = fmaf(w2, f2.x, acc0); acc1 = fmaf(w2, f2.y, acc1);
        acc0 = fmaf(w3, f3.x, acc0); acc1 = fmaf(w3, f3.y, acc1);
        den += (w0 + w1) + (w2 + w3);
    }
    for (int j = nq << 2; j < cnt; ++j) {
        int2 p = bucket[j];
        unsigned u = g_zh[p.x * 32 + lane];
        float w = __int_as_float(p.y);
        float2 f = __half22float2(*(__half2*)&u);
        acc0 = fmaf(w, f.x, acc0); acc1 = fmaf(w, f.y, acc1);
        den += w;
    }
    float inv = (cnt > 0) ? (1.0f / den) : 0.0f;
    float2 res = make_float2(acc0 * inv, acc1 * inv);
    ((float2*)out)[(size_t)gw * 32 + lane] = res;
}

// ---------------- launch ----------------
extern "C" void kernel_launch(void* const* d_in, const int* in_sizes, int n_in,
                              void* d_out, int out_size) {
    const float* h   = (const float*)d_in[0];
    const float* W   = (const float*)d_in[1];
    const float* a   = (const float*)d_in[2];
    const int*   src = (const int*)d_in[3];
    const int*   dst = (const int*)d_in[4];
    float* out = (float*)d_out;
    (void)in_sizes; (void)n_in; (void)out_size;

    k_prep<<<9, 256>>>(W, a);                                  // W frags + va/vd
    k_gemm<<<(N_NODES + 127) / 128, 256>>>(h);                 // HMMA; zeroes g_cnt
    k_edge<<<((N_EDGES / 4) + 255) / 256, 256>>>(src, dst);    // 4 edges / thread
    k_accum<<<(N_NODES * 32 + 255) / 256, 256>>>(out);
}

// round 13
// speedup vs baseline: 1.3153x; 1.1253x over previous
#include <cuda_runtime.h>
#include <cuda_fp16.h>
#include <cstdint>

#define N_NODES 100000
#define N_EDGES 3200000
#define D_IN    128
#define D_OUT   64
#define CAP     96      // max in-degree bucket capacity (actual max ~58 for Poisson(32))

// ---------------- scratch (static device globals; no allocation) ----------------
__device__ unsigned g_zh  [(size_t)N_NODES * 32];      // z as half2 (64 cols -> 32 words), 12.8 MB
__device__ float    g_ezs [N_NODES];                   // exp(h . va)  (zd cancels in softmax)
__device__ int      g_cnt [N_NODES];                   // bucket fill counts
__device__ int2     g_perm[(size_t)N_NODES * CAP];     // (src, bitcast(w)) buckets, 76.8 MB
__device__ uint2    g_wf  [8 * 8 * 32];                // W as HMMA B-fragments [kstep][ntile][lane]
__device__ float    g_va  [D_IN];                      // W @ a[:64]

// ---------------- K0: prep — W fragments + projected attention vector ----------------
__global__ void k_prep(const float* __restrict__ W, const float* __restrict__ a) {
    if (blockIdx.x < 8) {
        int t = blockIdx.x * 256 + threadIdx.x;       // 0..2047 = [kstep][ntile][lane]
        int lane = t & 31;
        int gid = lane >> 2, tig = lane & 3;
        int rest = t >> 5;
        int ntile = rest & 7, kstep = rest >> 3;
        int k0 = kstep * 16 + tig * 2;
        int n  = ntile * 8 + gid;
        // B frag (col-major k16n8): b0 = {W[k0][n], W[k0+1][n]}, b1 = {W[k0+8][n], W[k0+9][n]}
        __half2 b0 = __floats2half2_rn(W[k0 * 64 + n],       W[(k0 + 1) * 64 + n]);
        __half2 b1 = __floats2half2_rn(W[(k0 + 8) * 64 + n], W[(k0 + 9) * 64 + n]);
        g_wf[t] = make_uint2(*(unsigned*)&b0, *(unsigned*)&b1);
    } else {
        int k = threadIdx.x;
        if (k < D_IN) {
            float sa = 0.0f;
            #pragma unroll 8
            for (int n = 0; n < 64; ++n)
                sa = fmaf(W[k * 64 + n], a[n], sa);
            g_va[k] = sa;
        }
    }
}

// ---------------- K1: z = h @ W via HMMA m16n8k16; fused exp(h.va) ---------------------
// 8 warps/block, warp = 16 nodes x 64 cols. A frags straight from gmem (fp32->f16x2).
__global__ __launch_bounds__(256) void k_gemm(const float* __restrict__ h) {
    int warp = threadIdx.x >> 5, lane = threadIdx.x & 31;
    int gid = lane >> 2, tig = lane & 3;
    int M0 = blockIdx.x * 128 + warp * 16;
    if (M0 >= N_NODES) return;                         // 100000 % 16 == 0: full tiles only
    const float* rowA = h + (size_t)(M0 + gid) * D_IN;
    const float* rowB = h + (size_t)(M0 + 8 + gid) * D_IN;

    float d[8][4] = {};                                // [ntile][c0..c3]
    float zsA = 0.0f, zsB = 0.0f;

    #pragma unroll
    for (int ks = 0; ks < 8; ++ks) {
        int kA = ks * 16 + tig * 2;
        float2 fa0 = *(const float2*)&rowA[kA];        // A[gid][kA..+1]
        float2 fa1 = *(const float2*)&rowB[kA];        // A[gid+8][kA..+1]
        float2 fa2 = *(const float2*)&rowA[kA + 8];    // A[gid][kA+8..+9]
        float2 fa3 = *(const float2*)&rowB[kA + 8];    // A[gid+8][kA+8..+9]
        // exact fp32 logit partial: zs = h . va   (zd not needed: cancels in softmax)
        float2 vaL = *(const float2*)&g_va[kA];
        float2 vaH = *(const float2*)&g_va[kA + 8];
        zsA = fmaf(fa0.x, vaL.x, fmaf(fa0.y, vaL.y, fmaf(fa2.x, vaH.x, fmaf(fa2.y, vaH.y, zsA))));
        zsB = fmaf(fa1.x, vaL.x, fmaf(fa1.y, vaL.y, fmaf(fa3.x, vaH.x, fmaf(fa3.y, vaH.y, zsB))));
        // pack A frags to f16x2
        __half2 ha0 = __floats2half2_rn(fa0.x, fa0.y);
        __half2 ha1 = __floats2half2_rn(fa1.x, fa1.y);
        __half2 ha2 = __floats2half2_rn(fa2.x, fa2.y);
        __half2 ha3 = __floats2half2_rn(fa3.x, fa3.y);
        unsigned a0 = *(unsigned*)&ha0, a1 = *(unsigned*)&ha1;
        unsigned a2 = *(unsigned*)&ha2, a3 = *(unsigned*)&ha3;
        const uint2* wf = &g_wf[ks * 256 + lane];
        #pragma unroll
        for (int nt = 0; nt < 8; ++nt) {
            uint2 b = wf[nt * 32];
            asm volatile(
                "mma.sync.aligned.m16n8k16.row.col.f32.f16.f16.f32 "
                "{%0,%1,%2,%3}, {%4,%5,%6,%7}, {%8,%9}, {%0,%1,%2,%3};"
                : "+f"(d[nt][0]), "+f"(d[nt][1]), "+f"(d[nt][2]), "+f"(d[nt][3])
                : "r"(a0), "r"(a1), "r"(a2), "r"(a3), "r"(b.x), "r"(b.y));
        }
    }

    // z store: row M0+gid cols nt*8+tig*2(,+1) -> word nt*4+tig; row M0+8+gid from c2,c3
    unsigned* zr0 = &g_zh[(size_t)(M0 + gid) * 32];
    unsigned* zr1 = &g_zh[(size_t)(M0 + 8 + gid) * 32];
    #pragma unroll
    for (int nt = 0; nt < 8; ++nt) {
        __half2 p0 = __floats2half2_rn(d[nt][0], d[nt][1]);
        __half2 p1 = __floats2half2_rn(d[nt][2], d[nt][3]);
        zr0[nt * 4 + tig] = *(unsigned*)&p0;
        zr1[nt * 4 + tig] = *(unsigned*)&p1;
    }
    // reduce logits across the 4-lane tig group
    zsA += __shfl_xor_sync(0xffffffffu, zsA, 1); zsA += __shfl_xor_sync(0xffffffffu, zsA, 2);
    zsB += __shfl_xor_sync(0xffffffffu, zsB, 1); zsB += __shfl_xor_sync(0xffffffffu, zsB, 2);
    if (tig == 0) {
        int n1 = M0 + gid, n2 = M0 + 8 + gid;
        g_ezs[n1] = __expf(zsA); g_cnt[n1] = 0;
        g_ezs[n2] = __expf(zsB); g_cnt[n2] = 0;
    }
}

// ---------------- K2: edge pass (4 edges/thread): w = ezs[s], drop into dst bucket -----
__global__ void k_edge(const int* __restrict__ src, const int* __restrict__ dst) {
    int i = blockIdx.x * blockDim.x + threadIdx.x;   // quad index
    if (i * 4 >= N_EDGES) return;
    int4 s4 = ((const int4*)src)[i];
    int4 d4 = ((const int4*)dst)[i];
    // 4 gathers in flight (only src side needed: zd cancels in the softmax)
    float w0 = g_ezs[s4.x];
    float w1 = g_ezs[s4.y];
    float w2 = g_ezs[s4.z];
    float w3 = g_ezs[s4.w];
    int p0 = atomicAdd(&g_cnt[d4.x], 1);
    int p1 = atomicAdd(&g_cnt[d4.y], 1);
    int p2 = atomicAdd(&g_cnt[d4.z], 1);
    int p3 = atomicAdd(&g_cnt[d4.w], 1);
    g_perm[d4.x * CAP + p0] = make_int2(s4.x, __float_as_int(w0));
    g_perm[d4.y * CAP + p1] = make_int2(s4.y, __float_as_int(w1));
    g_perm[d4.z * CAP + p2] = make_int2(s4.z, __float_as_int(w2));
    g_perm[d4.w * CAP + p3] = make_int2(s4.w, __float_as_int(w3));
}

// ---------------- K3: warp-per-node accumulate (fp32 quad loop, known-good) ----------
__global__ __launch_bounds__(256) void k_accum(float* __restrict__ out) {
    int gw   = (blockIdx.x * 256 + threadIdx.x) >> 5;
    int lane = threadIdx.x & 31;
    if (gw >= N_NODES) return;
    int cnt  = g_cnt[gw];
    const int2* bucket = g_perm + (size_t)gw * CAP;
    const int4* b4     = (const int4*)bucket;

    float acc0 = 0.0f, acc1 = 0.0f, den = 0.0f;
    int nq = cnt >> 2;
    #pragma unroll 1
    for (int q = 0; q < nq; ++q) {
        int4 ba = b4[2 * q];
        int4 bb = b4[2 * q + 1];
        unsigned u0 = g_zh[ba.x * 32 + lane];
        unsigned u1 = g_zh[ba.z * 32 + lane];
        unsigned u2 = g_zh[bb.x * 32 + lane];
        unsigned u3 = g_zh[bb.z * 32 + lane];
        float w0 = __int_as_float(ba.y), w1 = __int_as_float(ba.w);
        float w2 = __int_as_float(bb.y), w3 = __int_as_float(bb.w);
        float2 f0 = __half22float2(*(__half2*)&u0);
        float2 f1 = __half22float2(*(__half2*)&u1);
        float2 f2 = __half22float2(*(__half2*)&u2);
        float2 f3 = __half22float2(*(__half2*)&u3);
        acc0 = fmaf(w0, f0.x, acc0); acc1 = fmaf(w0, f0.y, acc1);
        acc0 = fmaf(w1, f1.x, acc0); acc1 = fmaf(w1, f1.y, acc1);
        acc0 = fmaf(w2, f2.x, acc0); acc1 = fmaf(w2, f2.y, acc1);
        acc0 = fmaf(w3, f3.x, acc0); acc1 = fmaf(w3, f3.y, acc1);
        den += (w0 + w1) + (w2 + w3);
    }
    for (int j = nq << 2; j < cnt; ++j) {
        int2 p = bucket[j];
        unsigned u = g_zh[p.x * 32 + lane];
        float w = __int_as_float(p.y);
        float2 f = __half22float2(*(__half2*)&u);
        acc0 = fmaf(w, f.x, acc0); acc1 = fmaf(w, f.y, acc1);
        den += w;
    }
    float inv = (cnt > 0) ? (1.0f / den) : 0.0f;
    float2 res = make_float2(acc0 * inv, acc1 * inv);
    ((float2*)out)[(size_t)gw * 32 + lane] = res;
}

// ---------------- launch ----------------
extern "C" void kernel_launch(void* const* d_in, const int* in_sizes, int n_in,
                              void* d_out, int out_size) {
    const float* h   = (const float*)d_in[0];
    const float* W   = (const float*)d_in[1];
    const float* a   = (const float*)d_in[2];
    const int*   src = (const int*)d_in[3];
    const int*   dst = (const int*)d_in[4];
    float* out = (float*)d_out;
    (void)in_sizes; (void)n_in; (void)out_size;

    k_prep<<<9, 256>>>(W, a);                                  // W frags + va
    k_gemm<<<(N_NODES + 127) / 128, 256>>>(h);                 // HMMA; zeroes g_cnt
    k_edge<<<((N_EDGES / 4) + 255) / 256, 256>>>(src, dst);    // 4 edges / thread
    k_accum<<<(N_NODES * 32 + 255) / 256, 256>>>(out);
}